// round 6
// baseline (speedup 1.0000x reference)
#include <cuda_runtime.h>
#include <math.h>

#define N_CELLS  1024
#define L_DIM    30
#define G_GENES  10000
#define NB_BATCH 64
#define TG       128            // threads per block
#define GPB      256            // genes per block (2 per thread)
#define CMAX     112            // cells per smem chunk (even)

typedef unsigned long long ull;

__device__ __forceinline__ ull pack2(float lo, float hi) {
    ull r;
    asm("mov.b64 %0, {%1, %2};" : "=l"(r)
        : "r"(__float_as_uint(lo)), "r"(__float_as_uint(hi)));
    return r;
}
__device__ __forceinline__ void unpack2(ull v, float& lo, float& hi) {
    unsigned u0, u1;
    asm("mov.b64 {%0, %1}, %2;" : "=r"(u0), "=r"(u1) : "l"(v));
    lo = __uint_as_float(u0);
    hi = __uint_as_float(u1);
}
__device__ __forceinline__ ull fma2(ull a, ull b, ull c) {
    ull d;
    asm("fma.rn.f32x2 %0, %1, %2, %3;" : "=l"(d) : "l"(a), "l"(b), "l"(c));
    return d;
}
__device__ __forceinline__ float softplus_fast(float x) {
    return fmaxf(x, 0.f) + __logf(1.f + __expf(-fabsf(x)));
}

// ---------------------------------------------------------------------------
// grid = (ceil(G/GPB), NB). Each thread: 2 genes (gA = g0+tid, gB = gA+TG),
// so each z LDS.128 broadcast feeds 4 FFMA2 (2 genes x 2 cells) instead of 2.
// LDS warp-instruction count (the R5 bottleneck) halves.
// ---------------------------------------------------------------------------
__global__ __launch_bounds__(TG) void decoder_fused(
    const float* __restrict__ z,      // [N, L]
    const int*   __restrict__ batch,  // [N]
    const float* __restrict__ sf,     // [N, 1]
    const float* __restrict__ W,      // [L, G]
    const float* __restrict__ A,      // [NB, G, L]
    const float* __restrict__ Bemb,   // [NB, G]
    const float* __restrict__ px_r,   // [G]
    float* __restrict__ out)          // [N*G mean] ++ [G inv_disp]
{
    const int b   = blockIdx.y;
    const int g0  = blockIdx.x * GPB;
    const int tid = threadIdx.x;
    const int gA  = g0 + tid;
    const int gB  = g0 + TG + tid;
    const bool vA = (gA < G_GENES);
    const bool vB = (gB < G_GENES);

    // union: A chunk (GPB*30 floats = 30720B) OR z tile (CMAX x 32 = 14336B)
    __shared__ __align__(16) float s_buf[GPB * L_DIM];
    __shared__ unsigned short s_cidx[N_CELLS];
    __shared__ float s_sf[CMAX];
    __shared__ int   s_cnt;

    float (*s_z)[32] = reinterpret_cast<float(*)[32]>(s_buf);

    // ---- inverse dispersion (one row of blocks) ----
    if (b == 0) {
        if (vA) out[(size_t)N_CELLS * G_GENES + gA] = expf(px_r[gA]);
        if (vB) out[(size_t)N_CELLS * G_GENES + gB] = expf(px_r[gB]);
    }

    // ---- build this batch's cell list ----
    if (tid == 0) s_cnt = 0;
    __syncthreads();
    for (int i = tid; i < N_CELLS; i += TG)
        if (batch[i] == b)
            s_cidx[atomicAdd(&s_cnt, 1)] = (unsigned short)i;

    // ---- coalesced stage of A chunk ----
    {
        const int gv = min(GPB, G_GENES - g0);
        const float4* Ab = reinterpret_cast<const float4*>(
            A + ((size_t)b * G_GENES + g0) * L_DIM);
        float4* s4 = reinterpret_cast<float4*>(s_buf);
        const int nf4 = (gv * L_DIM) >> 2;
        for (int i = tid; i < nf4; i += TG) s4[i] = Ab[i];
    }
    __syncthreads();
    const int m = s_cnt;

    // ---- fused coefficients: 16 f32x2 pairs per gene (last = zero pad) ----
    ull cA[16], cB[16], iA = 0, iB = 0;
    {
        #pragma unroll
        for (int j = 0; j < 16; j++) { cA[j] = 0; cB[j] = 0; }
        if (vA) {
            float c[L_DIM];
            #pragma unroll
            for (int l = 0; l < L_DIM; l++)
                c[l] = W[(size_t)l * G_GENES + gA] + s_buf[tid * L_DIM + l];
            #pragma unroll
            for (int j = 0; j < 15; j++) cA[j] = pack2(c[2*j], c[2*j+1]);
            iA = pack2(Bemb[(size_t)b * G_GENES + gA], 0.f);
        }
        if (vB) {
            float c[L_DIM];
            #pragma unroll
            for (int l = 0; l < L_DIM; l++)
                c[l] = W[(size_t)l * G_GENES + gB] + s_buf[(tid+TG) * L_DIM + l];
            #pragma unroll
            for (int j = 0; j < 15; j++) cB[j] = pack2(c[2*j], c[2*j+1]);
            iB = pack2(Bemb[(size_t)b * G_GENES + gB], 0.f);
        }
    }

    // ---- main loop over this batch's cells ----
    for (int c0 = 0; c0 < m; c0 += CMAX) {
        const int mc  = min(CMAX, m - c0);
        const int mcp = (mc + 1) & ~1;
        __syncthreads();
        for (int i = tid; i < mcp * 32; i += TG) {
            int c = i >> 5, l = i & 31;
            float v = 0.f;
            if (l < L_DIM && c < mc)
                v = z[(int)s_cidx[c0 + c] * L_DIM + l];
            s_z[c][l] = v;
        }
        if (tid < mc) s_sf[tid] = sf[s_cidx[c0 + tid]];
        __syncthreads();

        for (int c = 0; c < mc; c += 2) {
            const ulonglong2* r0 = reinterpret_cast<const ulonglong2*>(s_z[c]);
            const ulonglong2* r1 = reinterpret_cast<const ulonglong2*>(s_z[c+1]);
            ull a0A = iA, a1A = iA, a0B = iB, a1B = iB;
            #pragma unroll
            for (int j = 0; j < 8; j++) {
                ulonglong2 v0 = r0[j];            // LDS.128 broadcast
                ulonglong2 v1 = r1[j];
                a0A = fma2(cA[2*j],   v0.x, a0A);
                a0A = fma2(cA[2*j+1], v0.y, a0A);
                a1A = fma2(cA[2*j],   v1.x, a1A);
                a1A = fma2(cA[2*j+1], v1.y, a1A);
                a0B = fma2(cB[2*j],   v0.x, a0B);
                a0B = fma2(cB[2*j+1], v0.y, a0B);
                a1B = fma2(cB[2*j],   v1.x, a1B);
                a1B = fma2(cB[2*j+1], v1.y, a1B);
            }
            float e, o;
            const size_t row0 = (size_t)s_cidx[c0 + c] * G_GENES;
            unpack2(a0A, e, o);
            float xA0 = e + o;
            unpack2(a0B, e, o);
            float xB0 = e + o;
            if (vA) out[row0 + gA] = softplus_fast(xA0) * s_sf[c];
            if (vB) out[row0 + gB] = softplus_fast(xB0) * s_sf[c];
            if (c + 1 < mc) {
                const size_t row1 = (size_t)s_cidx[c0 + c + 1] * G_GENES;
                unpack2(a1A, e, o);
                float xA1 = e + o;
                unpack2(a1B, e, o);
                float xB1 = e + o;
                if (vA) out[row1 + gA] = softplus_fast(xA1) * s_sf[c+1];
                if (vB) out[row1 + gB] = softplus_fast(xB1) * s_sf[c+1];
            }
        }
    }
}

// ---------------------------------------------------------------------------
extern "C" void kernel_launch(void* const* d_in, const int* in_sizes, int n_in,
                              void* d_out, int out_size) {
    const float* z     = (const float*)d_in[0];
    const int*   batch = (const int*)  d_in[1];
    const float* sf    = (const float*)d_in[2];
    const float* W     = (const float*)d_in[3];
    const float* A     = (const float*)d_in[4];
    const float* Bemb  = (const float*)d_in[5];
    const float* pxr   = (const float*)d_in[6];
    float* out = (float*)d_out;

    dim3 grid((G_GENES + GPB - 1) / GPB, NB_BATCH);
    decoder_fused<<<grid, TG>>>(z, batch, sf, W, A, Bemb, pxr, out);
}